// round 14
// baseline (speedup 1.0000x reference)
#include <cuda_runtime.h>
#include <cuda_fp16.h>
#include <math.h>
#include <stdint.h>

// ---------------- static problem config ----------------
#define NQ     13294
#define BATCH  2
#define MROWS  (BATCH * NQ)     // 26588
#define E_     256
#define F_     1024
#define CATN   640              // concat proj width: 256 (v) + 256 (off) + 128 (aw)
#define NHEAD  8
#define HDIM   32
#define NLVL   4
#define NPNT   4
#define EPS    1e-5f

// ---------------- scratch (static device globals; no allocation) ----------------
__device__ float  g_x   [MROWS * E_];    // fp32 residual stream
__device__ __half g_xh  [MROWS * E_];    // fp16 view for GEMM A
__device__ __half g_voa [MROWS * CATN];  // [v | off | aw-logits] fp16
__device__ __half g_samp[MROWS * E_];    // deform output (GEMM A)
__device__ float  g_tmp [MROWS * E_];    // fp32 branch output (pre-LN)
__device__ __half g_ffn [MROWS * F_];    // FFN hidden
__device__ __half g_wcat[E_ * CATN];
__device__ float  g_bcat[CATN];
__device__ __half g_wo  [E_ * E_];
__device__ __half g_wf1 [E_ * F_];
__device__ __half g_wf2 [F_ * E_];

__constant__ int c_w[NLVL]     = {100, 50, 25, 13};
__constant__ int c_h[NLVL]     = {100, 50, 25, 13};
__constant__ int c_start[NLVL] = {0, 10000, 12500, 13125};

// ---------------- prep kernels (2 launches total) ----------------
__global__ void src_copy_kernel(const float* __restrict__ src,
                                float* __restrict__ xf, __half* __restrict__ xh, int n) {
    int i = blockIdx.x * blockDim.x + threadIdx.x;
    if (i < n) { float v = src[i]; xf[i] = v; xh[i] = __float2half(v); }
}

#define WCAT_N (E_ * CATN)
#define WO_N   (E_ * E_)
#define WF1_N  (E_ * F_)
#define WF2_N  (F_ * E_)
#define PREP_TOTAL (WCAT_N + WO_N + WF1_N + WF2_N)

__global__ void prep_weights_kernel(
    const float* __restrict__ Wv, const float* __restrict__ Woff, const float* __restrict__ Waw,
    const float* __restrict__ bv, const float* __restrict__ boff, const float* __restrict__ baw,
    const float* __restrict__ Wo, const float* __restrict__ Wf1, const float* __restrict__ Wf2,
    __half* __restrict__ wcat, float* __restrict__ bcat,
    __half* __restrict__ wo, __half* __restrict__ wf1, __half* __restrict__ wf2)
{
    int i = blockIdx.x * blockDim.x + threadIdx.x;
    if (i < WCAT_N) {
        int r = i / CATN, c = i % CATN;
        float v;
        if (c < 256)      v = Wv  [r * 256 + c];
        else if (c < 512) v = Woff[r * 256 + (c - 256)];
        else              v = Waw [r * 128 + (c - 512)];
        wcat[i] = __float2half(v);
    } else if (i < WCAT_N + WO_N) {
        int j = i - WCAT_N;
        wo[j] = __float2half(Wo[j]);
    } else if (i < WCAT_N + WO_N + WF1_N) {
        int j = i - WCAT_N - WO_N;
        wf1[j] = __float2half(Wf1[j]);
    } else if (i < PREP_TOTAL) {
        int j = i - WCAT_N - WO_N - WF1_N;
        wf2[j] = __float2half(Wf2[j]);
    }
    if (i < CATN) {
        bcat[i] = (i < 256) ? bv[i] : (i < 512) ? boff[i - 256] : baw[i - 512];
    }
}

// ---------------- cp.async helpers ----------------
__device__ __forceinline__ void cp_async16(void* smem_dst, const void* gmem_src, bool pred) {
    uint32_t saddr = (uint32_t)__cvta_generic_to_shared(smem_dst);
    int sz = pred ? 16 : 0;
    asm volatile("cp.async.cg.shared.global [%0], [%1], 16, %2;\n"
                 :: "r"(saddr), "l"(gmem_src), "r"(sz));
}
#define CP_COMMIT() asm volatile("cp.async.commit_group;\n" ::: "memory")
#define CP_WAIT1()  asm volatile("cp.async.wait_group 1;\n" ::: "memory")

// ---------------- FP16 tensor-core GEMM ----------------
// 128x128x64 CTA tile, 128 threads (4 warps 2x2), warp tile 64x64:
// per k16 step 8 LDSM serve 32 MMA (2x the previous MMA-per-LDSM density).
// 3-stage cp.async pipeline.
#define TBM 128
#define TBN 128
#define TBK 64
#define APADH 72
#define BPADH 136
#define NSTAGE 3
#define AS_STAGE (TBM * APADH)
#define BS_STAGE (TBK * BPADH)
#define GEMM_SMEM_BYTES ((NSTAGE * (AS_STAGE + BS_STAGE)) * 2)   // 107520

__device__ __forceinline__ void mma_f16(
    float& d0, float& d1, float& d2, float& d3,
    uint32_t a0, uint32_t a1, uint32_t a2, uint32_t a3,
    uint32_t b0, uint32_t b1)
{
    asm volatile(
        "mma.sync.aligned.m16n8k16.row.col.f32.f16.f16.f32 "
        "{%0,%1,%2,%3}, {%4,%5,%6,%7}, {%8,%9}, {%0,%1,%2,%3};"
        : "+f"(d0), "+f"(d1), "+f"(d2), "+f"(d3)
        : "r"(a0), "r"(a1), "r"(a2), "r"(a3), "r"(b0), "r"(b1));
}

__device__ __forceinline__ void ldsm_x4(uint32_t& r0, uint32_t& r1, uint32_t& r2, uint32_t& r3,
                                        const __half* p) {
    uint32_t addr = (uint32_t)__cvta_generic_to_shared(p);
    asm volatile("ldmatrix.sync.aligned.m8n8.x4.shared.b16 {%0,%1,%2,%3}, [%4];"
                 : "=r"(r0), "=r"(r1), "=r"(r2), "=r"(r3) : "r"(addr));
}

__device__ __forceinline__ void ldsm_x4_trans(uint32_t& r0, uint32_t& r1, uint32_t& r2, uint32_t& r3,
                                              const __half* p) {
    uint32_t addr = (uint32_t)__cvta_generic_to_shared(p);
    asm volatile("ldmatrix.sync.aligned.m8n8.x4.trans.shared.b16 {%0,%1,%2,%3}, [%4];"
                 : "=r"(r0), "=r"(r1), "=r"(r2), "=r"(r3) : "r"(addr));
}

__global__ __launch_bounds__(128, 2) void gemm_f16(
    const __half* __restrict__ A, const __half* __restrict__ W,
    const float* __restrict__ bias, void* __restrict__ Cout,
    int M, int K, int N, int relu, int out_half)
{
    extern __shared__ __half sm[];
    __half* Asm = sm;
    __half* Bsm = sm + NSTAGE * AS_STAGE;

    const int tid = threadIdx.x;
    const int bm  = blockIdx.y * TBM;
    const int bn  = blockIdx.x * TBN;

    // A tile: 128 rows x 64 halves (128B/row). 1 thread/row, 8 x 16B chunks.
    const int row_a = tid;
    // B tile: 64 rows x 128 halves (256B/row). 2 threads/row, 8 x 16B chunks.
    const int row_b = tid >> 1;
    const int col_b = (tid & 1) << 6;      // 0 or 64 halves

    const bool a_ok = (bm + row_a) < M;

    const int w    = tid >> 5;             // 0..3
    const int wm   = (w & 1) * 64;
    const int wn   = (w >> 1) * 64;
    const int lane = tid & 31;
    const int gid  = lane >> 2;
    const int tig  = lane & 3;
    const int l16  = lane & 15;
    const int lhi  = (lane >> 4) << 3;

    float acc[4][8][4] = {};

    const int KT = K >> 6;

    const __half* Abase = A + (size_t)(bm + row_a) * K;
    const __half* Bbase = W + (size_t)row_b * N + bn + col_b;

    __half* asm_dst[NSTAGE];
    __half* bsm_dst[NSTAGE];
    #pragma unroll
    for (int s = 0; s < NSTAGE; s++) {
        asm_dst[s] = Asm + s * AS_STAGE + row_a * APADH;
        bsm_dst[s] = Bsm + s * BS_STAGE + row_b * BPADH + col_b;
    }

    #pragma unroll
    for (int s = 0; s < NSTAGE - 1; s++) {
        const int k0 = s << 6;
        #pragma unroll
        for (int i = 0; i < 8; i++) {
            cp_async16(asm_dst[s] + i * 8, Abase + k0 + i * 8, a_ok);
            cp_async16(bsm_dst[s] + i * 8, Bbase + (size_t)k0 * N + i * 8, true);
        }
        CP_COMMIT();
    }

    for (int kt = 0; kt < KT; kt++) {
        CP_WAIT1();
        __syncthreads();

        if (kt + NSTAGE - 1 < KT) {
            const int s  = (kt + NSTAGE - 1) % NSTAGE;
            const int k0 = (kt + NSTAGE - 1) << 6;
            #pragma unroll
            for (int i = 0; i < 8; i++) {
                cp_async16(asm_dst[s] + i * 8, Abase + k0 + i * 8, a_ok);
                cp_async16(bsm_dst[s] + i * 8, Bbase + (size_t)k0 * N + i * 8, true);
            }
        }
        CP_COMMIT();

        const __half* Ab = Asm + (kt % NSTAGE) * AS_STAGE;
        const __half* Bb = Bsm + (kt % NSTAGE) * BS_STAGE;

        #pragma unroll
        for (int ks = 0; ks < 4; ks++) {
            const int kk = ks << 4;
            uint32_t af[4][4];
            uint32_t bf[8][2];
            #pragma unroll
            for (int mt = 0; mt < 4; mt++) {
                const int r0 = wm + mt * 16;
                ldsm_x4(af[mt][0], af[mt][1], af[mt][2], af[mt][3],
                        Ab + (size_t)(r0 + l16) * APADH + kk + lhi);
            }
            #pragma unroll
            for (int pr = 0; pr < 4; pr++) {
                const int c0 = wn + pr * 16;
                ldsm_x4_trans(bf[pr * 2][0], bf[pr * 2][1], bf[pr * 2 + 1][0], bf[pr * 2 + 1][1],
                              Bb + (size_t)(kk + l16) * BPADH + c0 + lhi);
            }
            #pragma unroll
            for (int mt = 0; mt < 4; mt++)
                #pragma unroll
                for (int nt = 0; nt < 8; nt++)
                    mma_f16(acc[mt][nt][0], acc[mt][nt][1], acc[mt][nt][2], acc[mt][nt][3],
                            af[mt][0], af[mt][1], af[mt][2], af[mt][3],
                            bf[nt][0], bf[nt][1]);
        }
    }

    float*  Cf = (float*)Cout;
    __half* Ch = (__half*)Cout;
    #pragma unroll
    for (int mt = 0; mt < 4; mt++) {
        const int r0 = bm + wm + mt * 16 + gid;
        const int r1 = r0 + 8;
        #pragma unroll
        for (int nt = 0; nt < 8; nt++) {
            const int c = bn + wn + nt * 8 + tig * 2;
            const float b0 = bias[c], b1 = bias[c + 1];
            float v0 = acc[mt][nt][0] + b0;
            float v1 = acc[mt][nt][1] + b1;
            float v2 = acc[mt][nt][2] + b0;
            float v3 = acc[mt][nt][3] + b1;
            if (relu) {
                v0 = fmaxf(v0, 0.f); v1 = fmaxf(v1, 0.f);
                v2 = fmaxf(v2, 0.f); v3 = fmaxf(v3, 0.f);
            }
            if (out_half) {
                if (r0 < M) *(__half2*)(Ch + (size_t)r0 * N + c) = __floats2half2_rn(v0, v1);
                if (r1 < M) *(__half2*)(Ch + (size_t)r1 * N + c) = __floats2half2_rn(v2, v3);
            } else {
                if (r0 < M) *(float2*)(Cf + (size_t)r0 * N + c) = make_float2(v0, v1);
                if (r1 < M) *(float2*)(Cf + (size_t)r1 * N + c) = make_float2(v2, v3);
            }
        }
    }
}

// ---------------- multi-scale deformable attention (round-9 version) ----------------
__global__ __launch_bounds__(256) void deform_attn_kernel(
    const __half* __restrict__ voa, const float* __restrict__ ref,
    __half* __restrict__ out)
{
    const int gw = blockIdx.x * 8 + (threadIdx.x >> 5);
    if (gw >= MROWS * 4) return;
    const int lane = threadIdx.x & 31;
    const int hp = gw & 3;
    const int bn = gw >> 2;
    const int b  = bn / NQ;
    const int h  = hp * 2 + (lane >> 4);
    const int p  = lane & 15;
    const int lvl = p >> 2;

    const __half* offp = voa + (size_t)bn * CATN + 256 + h * 32;
    float ox = __half2float(offp[p * 2 + 0]);
    float oy = __half2float(offp[p * 2 + 1]);
    float logit = __half2float(voa[(size_t)bn * CATN + 512 + h * 16 + p]);

    float mx = logit;
    #pragma unroll
    for (int o = 8; o > 0; o >>= 1) mx = fmaxf(mx, __shfl_xor_sync(0xFFFFFFFFu, mx, o));
    float e = __expf(logit - mx);
    float ss = e;
    #pragma unroll
    for (int o = 8; o > 0; o >>= 1) ss += __shfl_xor_sync(0xFFFFFFFFu, ss, o);
    const float prob = e / ss;

    const int W = c_w[lvl], H = c_h[lvl], S = c_start[lvl];
    const float fw = (float)W, fh = (float)H;
    const float rx = ref[((size_t)bn * NLVL + lvl) * 2 + 0];
    const float ry = ref[((size_t)bn * NLVL + lvl) * 2 + 1];

    const float locx = rx + ox / fw;
    const float locy = ry + oy / fh;
    const float xs = locx * fw - 0.5f;
    const float ys = locy * fh - 0.5f;
    const float fxs = floorf(xs), fys = floorf(ys);
    const int x0 = (int)fxs, y0 = (int)fys;
    const float lx = xs - fxs, ly = ys - fys;
    const int x1 = x0 + 1, y1 = y0 + 1;

    const float vx0 = (x0 >= 0 && x0 < W) ? 1.f : 0.f;
    const float vx1 = (x1 >= 0 && x1 < W) ? 1.f : 0.f;
    const float vy0 = (y0 >= 0 && y0 < H) ? 1.f : 0.f;
    const float vy1 = (y1 >= 0 && y1 < H) ? 1.f : 0.f;

    float w00 = (1.f - lx) * (1.f - ly) * prob * vy0 * vx0;
    float w01 = lx * (1.f - ly) * prob * vy0 * vx1;
    float w10 = (1.f - lx) * ly * prob * vy1 * vx0;
    float w11 = lx * ly * prob * vy1 * vx1;

    const int x0c = min(max(x0, 0), W - 1);
    const int x1c = min(max(x1, 0), W - 1);
    const int y0c = min(max(y0, 0), H - 1);
    const int y1c = min(max(y1, 0), H - 1);

    int r00 = S + y0c * W + x0c;
    int r01 = S + y0c * W + x1c;
    int r10 = S + y1c * W + x0c;
    int r11 = S + y1c * W + x1c;

    const int l16 = lane & 15;
    const __half2* vbase = (const __half2*)(voa + (size_t)b * NQ * CATN + h * HDIM) + l16;
    const int ROWH2 = CATN / 2;

    float2 acc = make_float2(0.f, 0.f);

    #pragma unroll
    for (int q = 0; q < 16; q++) {
        const int   i00 = __shfl_sync(0xFFFFFFFFu, r00, q, 16);
        const int   i01 = __shfl_sync(0xFFFFFFFFu, r01, q, 16);
        const int   i10 = __shfl_sync(0xFFFFFFFFu, r10, q, 16);
        const int   i11 = __shfl_sync(0xFFFFFFFFu, r11, q, 16);
        const float a00 = __shfl_sync(0xFFFFFFFFu, w00, q, 16);
        const float a01 = __shfl_sync(0xFFFFFFFFu, w01, q, 16);
        const float a10 = __shfl_sync(0xFFFFFFFFu, w10, q, 16);
        const float a11 = __shfl_sync(0xFFFFFFFFu, w11, q, 16);

        const float2 f00 = __half22float2(vbase[(size_t)i00 * ROWH2]);
        const float2 f01 = __half22float2(vbase[(size_t)i01 * ROWH2]);
        const float2 f10 = __half22float2(vbase[(size_t)i10 * ROWH2]);
        const float2 f11 = __half22float2(vbase[(size_t)i11 * ROWH2]);

        acc.x += a00 * f00.x + a01 * f01.x + a10 * f10.x + a11 * f11.x;
        acc.y += a00 * f00.y + a01 * f01.y + a10 * f10.y + a11 * f11.y;
    }

    __half2* op = (__half2*)(out + (size_t)bn * E_ + h * HDIM) + l16;
    *op = __floats2half2_rn(acc.x, acc.y);
}

// ---------------- fused residual add + LayerNorm (warp per row) ----------------
__global__ __launch_bounds__(256) void add_ln_kernel(
    const float* __restrict__ x, const float* __restrict__ r,
    const float* __restrict__ gamma, const float* __restrict__ beta,
    float* __restrict__ out_f, __half* __restrict__ out_h, int M)
{
    int row = blockIdx.x * 8 + (threadIdx.x >> 5);
    if (row >= M) return;
    int lane = threadIdx.x & 31;

    const float* xp = x + (size_t)row * E_;
    const float* rp = r + (size_t)row * E_;

    float vals[8];
    float s = 0.f;
    #pragma unroll
    for (int i = 0; i < 8; i++) {
        vals[i] = xp[lane + i * 32] + rp[lane + i * 32];
        s += vals[i];
    }
    #pragma unroll
    for (int o = 16; o > 0; o >>= 1) s += __shfl_xor_sync(0xFFFFFFFFu, s, o);
    float mean = s * (1.f / E_);

    float vs = 0.f;
    #pragma unroll
    for (int i = 0; i < 8; i++) {
        float d = vals[i] - mean;
        vs += d * d;
    }
    #pragma unroll
    for (int o = 16; o > 0; o >>= 1) vs += __shfl_xor_sync(0xFFFFFFFFu, vs, o);
    float inv = rsqrtf(vs * (1.f / E_) + EPS);

    float* opf = out_f + (size_t)row * E_;
    #pragma unroll
    for (int i = 0; i < 8; i++) {
        int c = lane + i * 32;
        float v = (vals[i] - mean) * inv * gamma[c] + beta[c];
        opf[c] = v;
        if (out_h) out_h[(size_t)row * E_ + c] = __float2half(v);
    }
}

// ---------------- launcher ----------------
static inline void run_gemm(const __half* A, const __half* W, const float* b,
                            void* C, int M, int K, int Nc, int relu, int out_half) {
    dim3 grid(Nc / TBN, (M + TBM - 1) / TBM);
    gemm_f16<<<grid, 128, GEMM_SMEM_BYTES>>>(A, W, b, C, M, K, Nc, relu, out_half);
}

extern "C" void kernel_launch(void* const* d_in, const int* in_sizes, int n_in,
                              void* d_out, int out_size) {
    const float* src  = (const float*)d_in[0];
    const float* ref  = (const float*)d_in[1];
    const float* Woff = (const float*)d_in[4];
    const float* boff = (const float*)d_in[5];
    const float* Waw  = (const float*)d_in[6];
    const float* baw  = (const float*)d_in[7];
    const float* Wv   = (const float*)d_in[8];
    const float* bv   = (const float*)d_in[9];
    const float* Wo   = (const float*)d_in[10];
    const float* bo   = (const float*)d_in[11];
    const float* ln1g = (const float*)d_in[12];
    const float* ln1b = (const float*)d_in[13];
    const float* Wf1  = (const float*)d_in[14];
    const float* bf1  = (const float*)d_in[15];
    const float* Wf2  = (const float*)d_in[16];
    const float* bf2  = (const float*)d_in[17];
    const float* ln2g = (const float*)d_in[18];
    const float* ln2b = (const float*)d_in[19];
    float* out = (float*)d_out;

    cudaFuncSetAttribute(gemm_f16, cudaFuncAttributeMaxDynamicSharedMemorySize, GEMM_SMEM_BYTES);

    float *px, *ptmp, *pbcat;
    __half *pxh, *pvoa, *psamp, *pffn, *pwcat, *pwo, *pwf1, *pwf2;
    cudaGetSymbolAddress((void**)&px,    g_x);
    cudaGetSymbolAddress((void**)&pxh,   g_xh);
    cudaGetSymbolAddress((void**)&pvoa,  g_voa);
    cudaGetSymbolAddress((void**)&psamp, g_samp);
    cudaGetSymbolAddress((void**)&ptmp,  g_tmp);
    cudaGetSymbolAddress((void**)&pffn,  g_ffn);
    cudaGetSymbolAddress((void**)&pwcat, g_wcat);
    cudaGetSymbolAddress((void**)&pbcat, g_bcat);
    cudaGetSymbolAddress((void**)&pwo,   g_wo);
    cudaGetSymbolAddress((void**)&pwf1,  g_wf1);
    cudaGetSymbolAddress((void**)&pwf2,  g_wf2);

    const int M = MROWS;
    const int nElem = M * E_;

    src_copy_kernel<<<(nElem + 255) / 256, 256>>>(src, px, pxh, nElem);
    prep_weights_kernel<<<(PREP_TOTAL + 255) / 256, 256>>>(
        Wv, Woff, Waw, bv, boff, baw, Wo, Wf1, Wf2,
        pwcat, pbcat, pwo, pwf1, pwf2);

    const int dwarps = M * 4;
    const int dgrid  = (dwarps + 7) / 8;

    for (int layer = 0; layer < 6; layer++) {
        // fused projections: [v | off | aw-logits], fp16 out
        run_gemm(pxh, pwcat, pbcat, pvoa, M, E_, CATN, 0, 1);

        deform_attn_kernel<<<dgrid, 256>>>(pvoa, ref, psamp);

        run_gemm(psamp, pwo, bo, ptmp, M, E_, E_, 0, 0);                 // fp32 out
        add_ln_kernel<<<(M + 7) / 8, 256>>>(px, ptmp, ln1g, ln1b, px, pxh, M);

        run_gemm(pxh,  pwf1, bf1, pffn, M, E_, F_, 1, 1);                // relu, fp16 out
        run_gemm(pffn, pwf2, bf2, ptmp, M, F_, E_, 0, 0);                // fp32 out

        float* dst = (layer == 5) ? out : px;
        __half* dsth = (layer == 5) ? (__half*)nullptr : pxh;
        add_ln_kernel<<<(M + 7) / 8, 256>>>(px, ptmp, ln2g, ln2b, dst, dsth, M);
    }
}

// round 15
// speedup vs baseline: 1.1548x; 1.1548x over previous
#include <cuda_runtime.h>
#include <cuda_fp16.h>
#include <math.h>
#include <stdint.h>

// ---------------- static problem config ----------------
#define NQ     13294
#define BATCH  2
#define MROWS  (BATCH * NQ)     // 26588
#define E_     256
#define F_     1024
#define CATN   640              // concat proj width: 256 (v) + 256 (off) + 128 (aw)
#define NHEAD  8
#define HDIM   32
#define NLVL   4
#define NPNT   4
#define EPS    1e-5f

// ---------------- scratch (static device globals; no allocation) ----------------
__device__ float  g_x   [MROWS * E_];    // fp32 residual stream
__device__ __half g_xh  [MROWS * E_];    // fp16 view for GEMM A
__device__ __half g_voa [MROWS * CATN];  // [v | off | aw-logits] fp16
__device__ __half g_samp[MROWS * E_];    // deform output (GEMM A)
__device__ float  g_tmp [MROWS * E_];    // fp32 branch output (pre-LN)
__device__ __half g_ffn [MROWS * F_];    // FFN hidden
__device__ __half g_wcat[E_ * CATN];
__device__ float  g_bcat[CATN];
__device__ __half g_wo  [E_ * E_];
__device__ __half g_wf1 [E_ * F_];
__device__ __half g_wf2 [F_ * E_];

__constant__ int c_w[NLVL]     = {100, 50, 25, 13};
__constant__ int c_h[NLVL]     = {100, 50, 25, 13};
__constant__ int c_start[NLVL] = {0, 10000, 12500, 13125};

// ---------------- prep kernels (2 launches total) ----------------
__global__ void src_copy_kernel(const float* __restrict__ src,
                                float* __restrict__ xf, __half* __restrict__ xh, int n) {
    int i = blockIdx.x * blockDim.x + threadIdx.x;
    if (i < n) { float v = src[i]; xf[i] = v; xh[i] = __float2half(v); }
}

#define WCAT_N (E_ * CATN)
#define WO_N   (E_ * E_)
#define WF1_N  (E_ * F_)
#define WF2_N  (F_ * E_)
#define PREP_TOTAL (WCAT_N + WO_N + WF1_N + WF2_N)

__global__ void prep_weights_kernel(
    const float* __restrict__ Wv, const float* __restrict__ Woff, const float* __restrict__ Waw,
    const float* __restrict__ bv, const float* __restrict__ boff, const float* __restrict__ baw,
    const float* __restrict__ Wo, const float* __restrict__ Wf1, const float* __restrict__ Wf2,
    __half* __restrict__ wcat, float* __restrict__ bcat,
    __half* __restrict__ wo, __half* __restrict__ wf1, __half* __restrict__ wf2)
{
    int i = blockIdx.x * blockDim.x + threadIdx.x;
    if (i < WCAT_N) {
        int r = i / CATN, c = i % CATN;
        float v;
        if (c < 256)      v = Wv  [r * 256 + c];
        else if (c < 512) v = Woff[r * 256 + (c - 256)];
        else              v = Waw [r * 128 + (c - 512)];
        wcat[i] = __float2half(v);
    } else if (i < WCAT_N + WO_N) {
        int j = i - WCAT_N;
        wo[j] = __float2half(Wo[j]);
    } else if (i < WCAT_N + WO_N + WF1_N) {
        int j = i - WCAT_N - WO_N;
        wf1[j] = __float2half(Wf1[j]);
    } else if (i < PREP_TOTAL) {
        int j = i - WCAT_N - WO_N - WF1_N;
        wf2[j] = __float2half(Wf2[j]);
    }
    if (i < CATN) {
        bcat[i] = (i < 256) ? bv[i] : (i < 512) ? boff[i - 256] : baw[i - 512];
    }
}

// ---------------- cp.async helpers ----------------
__device__ __forceinline__ void cp_async16(void* smem_dst, const void* gmem_src, bool pred) {
    uint32_t saddr = (uint32_t)__cvta_generic_to_shared(smem_dst);
    int sz = pred ? 16 : 0;
    asm volatile("cp.async.cg.shared.global [%0], [%1], 16, %2;\n"
                 :: "r"(saddr), "l"(gmem_src), "r"(sz));
}
#define CP_COMMIT() asm volatile("cp.async.commit_group;\n" ::: "memory")
#define CP_WAIT1()  asm volatile("cp.async.wait_group 1;\n" ::: "memory")

// ---------------- FP16 tensor-core GEMM (round-9 config: 256 thr, warp 64x32) ----------------
#define TBM 128
#define TBN 128
#define TBK 64
#define APADH 72
#define BPADH 136
#define NSTAGE 3
#define AS_STAGE (TBM * APADH)
#define BS_STAGE (TBK * BPADH)
#define GEMM_SMEM_BYTES ((NSTAGE * (AS_STAGE + BS_STAGE)) * 2)   // 107520

__device__ __forceinline__ void mma_f16(
    float& d0, float& d1, float& d2, float& d3,
    uint32_t a0, uint32_t a1, uint32_t a2, uint32_t a3,
    uint32_t b0, uint32_t b1)
{
    asm volatile(
        "mma.sync.aligned.m16n8k16.row.col.f32.f16.f16.f32 "
        "{%0,%1,%2,%3}, {%4,%5,%6,%7}, {%8,%9}, {%0,%1,%2,%3};"
        : "+f"(d0), "+f"(d1), "+f"(d2), "+f"(d3)
        : "r"(a0), "r"(a1), "r"(a2), "r"(a3), "r"(b0), "r"(b1));
}

__device__ __forceinline__ void ldsm_x4(uint32_t& r0, uint32_t& r1, uint32_t& r2, uint32_t& r3,
                                        const __half* p) {
    uint32_t addr = (uint32_t)__cvta_generic_to_shared(p);
    asm volatile("ldmatrix.sync.aligned.m8n8.x4.shared.b16 {%0,%1,%2,%3}, [%4];"
                 : "=r"(r0), "=r"(r1), "=r"(r2), "=r"(r3) : "r"(addr));
}

__device__ __forceinline__ void ldsm_x4_trans(uint32_t& r0, uint32_t& r1, uint32_t& r2, uint32_t& r3,
                                              const __half* p) {
    uint32_t addr = (uint32_t)__cvta_generic_to_shared(p);
    asm volatile("ldmatrix.sync.aligned.m8n8.x4.trans.shared.b16 {%0,%1,%2,%3}, [%4];"
                 : "=r"(r0), "=r"(r1), "=r"(r2), "=r"(r3) : "r"(addr));
}

__global__ __launch_bounds__(256, 2) void gemm_f16(
    const __half* __restrict__ A, const __half* __restrict__ W,
    const float* __restrict__ bias, void* __restrict__ Cout,
    int M, int K, int N, int relu, int out_half)
{
    extern __shared__ __half sm[];
    __half* Asm = sm;
    __half* Bsm = sm + NSTAGE * AS_STAGE;

    const int tid = threadIdx.x;
    const int bm  = blockIdx.y * TBM;
    const int bn  = blockIdx.x * TBN;

    const int row_a = tid >> 1;
    const int col_a = (tid & 1) << 5;
    const int row_b = tid >> 2;
    const int col_b = (tid & 3) << 5;

    const bool a_ok = (bm + row_a) < M;

    const int w    = tid >> 5;
    const int wm   = (w & 1) * 64;
    const int wn   = (w >> 1) * 32;
    const int lane = tid & 31;
    const int gid  = lane >> 2;
    const int tig  = lane & 3;
    const int l16  = lane & 15;
    const int lhi  = (lane >> 4) << 3;

    float acc[4][4][4] = {};

    const int KT = K >> 6;

    const __half* Abase = A + (size_t)(bm + row_a) * K + col_a;
    const __half* Bbase = W + (size_t)row_b * N + bn + col_b;

    __half* asm_dst[NSTAGE];
    __half* bsm_dst[NSTAGE];
    #pragma unroll
    for (int s = 0; s < NSTAGE; s++) {
        asm_dst[s] = Asm + s * AS_STAGE + row_a * APADH + col_a;
        bsm_dst[s] = Bsm + s * BS_STAGE + row_b * BPADH + col_b;
    }

    #pragma unroll
    for (int s = 0; s < NSTAGE - 1; s++) {
        const int k0 = s << 6;
        #pragma unroll
        for (int i = 0; i < 4; i++) {
            cp_async16(asm_dst[s] + i * 8, Abase + k0 + i * 8, a_ok);
            cp_async16(bsm_dst[s] + i * 8, Bbase + (size_t)k0 * N + i * 8, true);
        }
        CP_COMMIT();
    }

    for (int kt = 0; kt < KT; kt++) {
        CP_WAIT1();
        __syncthreads();

        if (kt + NSTAGE - 1 < KT) {
            const int s  = (kt + NSTAGE - 1) % NSTAGE;
            const int k0 = (kt + NSTAGE - 1) << 6;
            #pragma unroll
            for (int i = 0; i < 4; i++) {
                cp_async16(asm_dst[s] + i * 8, Abase + k0 + i * 8, a_ok);
                cp_async16(bsm_dst[s] + i * 8, Bbase + (size_t)k0 * N + i * 8, true);
            }
        }
        CP_COMMIT();

        const __half* Ab = Asm + (kt % NSTAGE) * AS_STAGE;
        const __half* Bb = Bsm + (kt % NSTAGE) * BS_STAGE;

        #pragma unroll
        for (int ks = 0; ks < 4; ks++) {
            const int kk = ks << 4;
            uint32_t af[4][4];
            uint32_t bf[4][2];
            #pragma unroll
            for (int mt = 0; mt < 4; mt++) {
                const int r0 = wm + mt * 16;
                ldsm_x4(af[mt][0], af[mt][1], af[mt][2], af[mt][3],
                        Ab + (size_t)(r0 + l16) * APADH + kk + lhi);
            }
            #pragma unroll
            for (int pr = 0; pr < 2; pr++) {
                const int c0 = wn + pr * 16;
                ldsm_x4_trans(bf[pr * 2][0], bf[pr * 2][1], bf[pr * 2 + 1][0], bf[pr * 2 + 1][1],
                              Bb + (size_t)(kk + l16) * BPADH + c0 + lhi);
            }
            #pragma unroll
            for (int mt = 0; mt < 4; mt++)
                #pragma unroll
                for (int nt = 0; nt < 4; nt++)
                    mma_f16(acc[mt][nt][0], acc[mt][nt][1], acc[mt][nt][2], acc[mt][nt][3],
                            af[mt][0], af[mt][1], af[mt][2], af[mt][3],
                            bf[nt][0], bf[nt][1]);
        }
    }

    float*  Cf = (float*)Cout;
    __half* Ch = (__half*)Cout;
    #pragma unroll
    for (int mt = 0; mt < 4; mt++) {
        const int r0 = bm + wm + mt * 16 + gid;
        const int r1 = r0 + 8;
        #pragma unroll
        for (int nt = 0; nt < 4; nt++) {
            const int c = bn + wn + nt * 8 + tig * 2;
            const float b0 = bias[c], b1 = bias[c + 1];
            float v0 = acc[mt][nt][0] + b0;
            float v1 = acc[mt][nt][1] + b1;
            float v2 = acc[mt][nt][2] + b0;
            float v3 = acc[mt][nt][3] + b1;
            if (relu) {
                v0 = fmaxf(v0, 0.f); v1 = fmaxf(v1, 0.f);
                v2 = fmaxf(v2, 0.f); v3 = fmaxf(v3, 0.f);
            }
            if (out_half) {
                if (r0 < M) *(__half2*)(Ch + (size_t)r0 * N + c) = __floats2half2_rn(v0, v1);
                if (r1 < M) *(__half2*)(Ch + (size_t)r1 * N + c) = __floats2half2_rn(v2, v3);
            } else {
                if (r0 < M) *(float2*)(Cf + (size_t)r0 * N + c) = make_float2(v0, v1);
                if (r1 < M) *(float2*)(Cf + (size_t)r1 * N + c) = make_float2(v2, v3);
            }
        }
    }
}

// ---------------- multi-scale deformable attention (round-9 + byte-offset shuffles) ----------------
// One warp = (query, head-pair); lanes 0-15 head h0, 16-31 head h1; each lane
// computes ONE point's params. Gather loop broadcasts PRE-MULTIPLIED byte
// offsets (idx * row_bytes computed once in phase 1) so consumer lanes do
// only pointer-add, removing 4 IMADs per point from the hot loop.
#define VROW_BYTES (CATN * 2)      // 1280 bytes per value row

__global__ __launch_bounds__(256) void deform_attn_kernel(
    const __half* __restrict__ voa, const float* __restrict__ ref,
    __half* __restrict__ out)
{
    const int gw = blockIdx.x * 8 + (threadIdx.x >> 5);
    if (gw >= MROWS * 4) return;
    const int lane = threadIdx.x & 31;
    const int hp = gw & 3;
    const int bn = gw >> 2;
    const int b  = bn / NQ;
    const int h  = hp * 2 + (lane >> 4);
    const int p  = lane & 15;
    const int lvl = p >> 2;

    // ---- phase 1: per-lane point math ----
    const __half* offp = voa + (size_t)bn * CATN + 256 + h * 32;
    float ox = __half2float(offp[p * 2 + 0]);
    float oy = __half2float(offp[p * 2 + 1]);
    float logit = __half2float(voa[(size_t)bn * CATN + 512 + h * 16 + p]);

    float mx = logit;
    #pragma unroll
    for (int o = 8; o > 0; o >>= 1) mx = fmaxf(mx, __shfl_xor_sync(0xFFFFFFFFu, mx, o));
    float e = __expf(logit - mx);
    float ss = e;
    #pragma unroll
    for (int o = 8; o > 0; o >>= 1) ss += __shfl_xor_sync(0xFFFFFFFFu, ss, o);
    const float prob = e / ss;

    const int W = c_w[lvl], H = c_h[lvl], S = c_start[lvl];
    const float fw = (float)W, fh = (float)H;
    const float rx = ref[((size_t)bn * NLVL + lvl) * 2 + 0];
    const float ry = ref[((size_t)bn * NLVL + lvl) * 2 + 1];

    const float locx = rx + ox / fw;
    const float locy = ry + oy / fh;
    const float xs = locx * fw - 0.5f;
    const float ys = locy * fh - 0.5f;
    const float fxs = floorf(xs), fys = floorf(ys);
    const int x0 = (int)fxs, y0 = (int)fys;
    const float lx = xs - fxs, ly = ys - fys;
    const int x1 = x0 + 1, y1 = y0 + 1;

    const float vx0 = (x0 >= 0 && x0 < W) ? 1.f : 0.f;
    const float vx1 = (x1 >= 0 && x1 < W) ? 1.f : 0.f;
    const float vy0 = (y0 >= 0 && y0 < H) ? 1.f : 0.f;
    const float vy1 = (y1 >= 0 && y1 < H) ? 1.f : 0.f;

    float w00 = (1.f - lx) * (1.f - ly) * prob * vy0 * vx0;
    float w01 = lx * (1.f - ly) * prob * vy0 * vx1;
    float w10 = (1.f - lx) * ly * prob * vy1 * vx0;
    float w11 = lx * ly * prob * vy1 * vx1;

    const int x0c = min(max(x0, 0), W - 1);
    const int x1c = min(max(x1, 0), W - 1);
    const int y0c = min(max(y0, 0), H - 1);
    const int y1c = min(max(y1, 0), H - 1);

    // pre-multiplied byte offsets (idx * 1280; max ~17M, fits int)
    int o00 = (S + y0c * W + x0c) * VROW_BYTES;
    int o01 = (S + y0c * W + x1c) * VROW_BYTES;
    int o10 = (S + y1c * W + x0c) * VROW_BYTES;
    int o11 = (S + y1c * W + x1c) * VROW_BYTES;

    // ---- phase 2: gather 32 channels per head (16 lanes x half2) ----
    const int l16 = lane & 15;
    const char* vb = (const char*)(voa + (size_t)b * NQ * CATN + h * HDIM) + l16 * 4;

    float2 acc = make_float2(0.f, 0.f);

    #pragma unroll
    for (int q = 0; q < 16; q++) {
        const int   b00 = __shfl_sync(0xFFFFFFFFu, o00, q, 16);
        const int   b01 = __shfl_sync(0xFFFFFFFFu, o01, q, 16);
        const int   b10 = __shfl_sync(0xFFFFFFFFu, o10, q, 16);
        const int   b11 = __shfl_sync(0xFFFFFFFFu, o11, q, 16);
        const float a00 = __shfl_sync(0xFFFFFFFFu, w00, q, 16);
        const float a01 = __shfl_sync(0xFFFFFFFFu, w01, q, 16);
        const float a10 = __shfl_sync(0xFFFFFFFFu, w10, q, 16);
        const float a11 = __shfl_sync(0xFFFFFFFFu, w11, q, 16);

        const float2 f00 = __half22float2(*(const __half2*)(vb + b00));
        const float2 f01 = __half22float2(*(const __half2*)(vb + b01));
        const float2 f10 = __half22float2(*(const __half2*)(vb + b10));
        const float2 f11 = __half22float2(*(const __half2*)(vb + b11));

        acc.x += a00 * f00.x + a01 * f01.x + a10 * f10.x + a11 * f11.x;
        acc.y += a00 * f00.y + a01 * f01.y + a10 * f10.y + a11 * f11.y;
    }

    __half2* op = (__half2*)(out + (size_t)bn * E_ + h * HDIM) + l16;
    *op = __floats2half2_rn(acc.x, acc.y);
}

// ---------------- fused residual add + LayerNorm (warp per row) ----------------
__global__ __launch_bounds__(256) void add_ln_kernel(
    const float* __restrict__ x, const float* __restrict__ r,
    const float* __restrict__ gamma, const float* __restrict__ beta,
    float* __restrict__ out_f, __half* __restrict__ out_h, int M)
{
    int row = blockIdx.x * 8 + (threadIdx.x >> 5);
    if (row >= M) return;
    int lane = threadIdx.x & 31;

    const float* xp = x + (size_t)row * E_;
    const float* rp = r + (size_t)row * E_;

    float vals[8];
    float s = 0.f;
    #pragma unroll
    for (int i = 0; i < 8; i++) {
        vals[i] = xp[lane + i * 32] + rp[lane + i * 32];
        s += vals[i];
    }
    #pragma unroll
    for (int o = 16; o > 0; o >>= 1) s += __shfl_xor_sync(0xFFFFFFFFu, s, o);
    float mean = s * (1.f / E_);

    float vs = 0.f;
    #pragma unroll
    for (int i = 0; i < 8; i++) {
        float d = vals[i] - mean;
        vs += d * d;
    }
    #pragma unroll
    for (int o = 16; o > 0; o >>= 1) vs += __shfl_xor_sync(0xFFFFFFFFu, vs, o);
    float inv = rsqrtf(vs * (1.f / E_) + EPS);

    float* opf = out_f + (size_t)row * E_;
    #pragma unroll
    for (int i = 0; i < 8; i++) {
        int c = lane + i * 32;
        float v = (vals[i] - mean) * inv * gamma[c] + beta[c];
        opf[c] = v;
        if (out_h) out_h[(size_t)row * E_ + c] = __float2half(v);
    }
}

// ---------------- launcher ----------------
static inline void run_gemm(const __half* A, const __half* W, const float* b,
                            void* C, int M, int K, int Nc, int relu, int out_half) {
    dim3 grid(Nc / TBN, (M + TBM - 1) / TBM);
    gemm_f16<<<grid, 256, GEMM_SMEM_BYTES>>>(A, W, b, C, M, K, Nc, relu, out_half);
}

extern "C" void kernel_launch(void* const* d_in, const int* in_sizes, int n_in,
                              void* d_out, int out_size) {
    const float* src  = (const float*)d_in[0];
    const float* ref  = (const float*)d_in[1];
    const float* Woff = (const float*)d_in[4];
    const float* boff = (const float*)d_in[5];
    const float* Waw  = (const float*)d_in[6];
    const float* baw  = (const float*)d_in[7];
    const float* Wv   = (const float*)d_in[8];
    const float* bv   = (const float*)d_in[9];
    const float* Wo   = (const float*)d_in[10];
    const float* bo   = (const float*)d_in[11];
    const float* ln1g = (const float*)d_in[12];
    const float* ln1b = (const float*)d_in[13];
    const float* Wf1  = (const float*)d_in[14];
    const float* bf1  = (const float*)d_in[15];
    const float* Wf2  = (const float*)d_in[16];
    const float* bf2  = (const float*)d_in[17];
    const float* ln2g = (const float*)d_in[18];
    const float* ln2b = (const float*)d_in[19];
    float* out = (float*)d_out;

    cudaFuncSetAttribute(gemm_f16, cudaFuncAttributeMaxDynamicSharedMemorySize, GEMM_SMEM_BYTES);

    float *px, *ptmp, *pbcat;
    __half *pxh, *pvoa, *psamp, *pffn, *pwcat, *pwo, *pwf1, *pwf2;
    cudaGetSymbolAddress((void**)&px,    g_x);
    cudaGetSymbolAddress((void**)&pxh,   g_xh);
    cudaGetSymbolAddress((void**)&pvoa,  g_voa);
    cudaGetSymbolAddress((void**)&psamp, g_samp);
    cudaGetSymbolAddress((void**)&ptmp,  g_tmp);
    cudaGetSymbolAddress((void**)&pffn,  g_ffn);
    cudaGetSymbolAddress((void**)&pwcat, g_wcat);
    cudaGetSymbolAddress((void**)&pbcat, g_bcat);
    cudaGetSymbolAddress((void**)&pwo,   g_wo);
    cudaGetSymbolAddress((void**)&pwf1,  g_wf1);
    cudaGetSymbolAddress((void**)&pwf2,  g_wf2);

    const int M = MROWS;
    const int nElem = M * E_;

    src_copy_kernel<<<(nElem + 255) / 256, 256>>>(src, px, pxh, nElem);
    prep_weights_kernel<<<(PREP_TOTAL + 255) / 256, 256>>>(
        Wv, Woff, Waw, bv, boff, baw, Wo, Wf1, Wf2,
        pwcat, pbcat, pwo, pwf1, pwf2);

    const int dwarps = M * 4;
    const int dgrid  = (dwarps + 7) / 8;

    for (int layer = 0; layer < 6; layer++) {
        // fused projections: [v | off | aw-logits], fp16 out
        run_gemm(pxh, pwcat, pbcat, pvoa, M, E_, CATN, 0, 1);

        deform_attn_kernel<<<dgrid, 256>>>(pvoa, ref, psamp);

        run_gemm(psamp, pwo, bo, ptmp, M, E_, E_, 0, 0);                 // fp32 out
        add_ln_kernel<<<(M + 7) / 8, 256>>>(px, ptmp, ln1g, ln1b, px, pxh, M);

        run_gemm(pxh,  pwf1, bf1, pffn, M, E_, F_, 1, 1);                // relu, fp16 out
        run_gemm(pffn, pwf2, bf2, ptmp, M, F_, E_, 0, 0);                // fp32 out

        float* dst = (layer == 5) ? out : px;
        __half* dsth = (layer == 5) ? (__half*)nullptr : pxh;
        add_ln_kernel<<<(M + 7) / 8, 256>>>(px, ptmp, ln2g, ln2b, dst, dsth, M);
    }
}

// round 16
// speedup vs baseline: 1.1585x; 1.0033x over previous
#include <cuda_runtime.h>
#include <cuda_fp16.h>
#include <math.h>
#include <stdint.h>

// ---------------- static problem config ----------------
#define NQ     13294
#define BATCH  2
#define MROWS  (BATCH * NQ)     // 26588
#define E_     256
#define F_     1024
#define CATN   640              // concat proj width: 256 (v) + 256 (off) + 128 (aw)
#define NHEAD  8
#define HDIM   32
#define NLVL   4
#define NPNT   4
#define EPS    1e-5f

// ---------------- scratch (static device globals; no allocation) ----------------
__device__ float  g_x   [MROWS * E_];    // fp32 residual stream
__device__ __half g_xh  [MROWS * E_];    // fp16 view for GEMM A
__device__ __half g_voa [MROWS * CATN];  // [v | off | aw-logits] fp16
__device__ __half g_samp[MROWS * E_];    // deform output (GEMM A)
__device__ float  g_tmp [MROWS * E_];    // fp32 branch output (pre-LN)
__device__ __half g_ffn [MROWS * F_];    // FFN hidden
__device__ __half g_wcat[E_ * CATN];
__device__ float  g_bcat[CATN];
__device__ __half g_wo  [E_ * E_];
__device__ __half g_wf1 [E_ * F_];
__device__ __half g_wf2 [F_ * E_];

__constant__ int c_w[NLVL]     = {100, 50, 25, 13};
__constant__ int c_h[NLVL]     = {100, 50, 25, 13};
__constant__ int c_start[NLVL] = {0, 10000, 12500, 13125};

// ---------------- single prep kernel (1 launch) ----------------
#define XCOPY_N (MROWS * E_)    // 6806528
#define WCAT_N (E_ * CATN)
#define WO_N   (E_ * E_)
#define WF1_N  (E_ * F_)
#define WF2_N  (F_ * E_)
#define PREP_TOTAL (XCOPY_N + WCAT_N + WO_N + WF1_N + WF2_N)

__global__ void prep_all_kernel(
    const float* __restrict__ src,
    const float* __restrict__ Wv, const float* __restrict__ Woff, const float* __restrict__ Waw,
    const float* __restrict__ bv, const float* __restrict__ boff, const float* __restrict__ baw,
    const float* __restrict__ Wo, const float* __restrict__ Wf1, const float* __restrict__ Wf2,
    float* __restrict__ xf, __half* __restrict__ xh,
    __half* __restrict__ wcat, float* __restrict__ bcat,
    __half* __restrict__ wo, __half* __restrict__ wf1, __half* __restrict__ wf2)
{
    int i = blockIdx.x * blockDim.x + threadIdx.x;
    if (i < XCOPY_N) {
        float v = src[i]; xf[i] = v; xh[i] = __float2half(v);
    } else if (i < XCOPY_N + WCAT_N) {
        int j = i - XCOPY_N;
        int r = j / CATN, c = j % CATN;
        float v;
        if (c < 256)      v = Wv  [r * 256 + c];
        else if (c < 512) v = Woff[r * 256 + (c - 256)];
        else              v = Waw [r * 128 + (c - 512)];
        wcat[j] = __float2half(v);
    } else if (i < XCOPY_N + WCAT_N + WO_N) {
        int j = i - XCOPY_N - WCAT_N;
        wo[j] = __float2half(Wo[j]);
    } else if (i < XCOPY_N + WCAT_N + WO_N + WF1_N) {
        int j = i - XCOPY_N - WCAT_N - WO_N;
        wf1[j] = __float2half(Wf1[j]);
    } else if (i < PREP_TOTAL) {
        int j = i - XCOPY_N - WCAT_N - WO_N - WF1_N;
        wf2[j] = __float2half(Wf2[j]);
    }
    if (i < CATN) {
        bcat[i] = (i < 256) ? bv[i] : (i < 512) ? boff[i - 256] : baw[i - 512];
    }
}

// ---------------- cp.async helpers ----------------
__device__ __forceinline__ void cp_async16(void* smem_dst, const void* gmem_src, bool pred) {
    uint32_t saddr = (uint32_t)__cvta_generic_to_shared(smem_dst);
    int sz = pred ? 16 : 0;
    asm volatile("cp.async.cg.shared.global [%0], [%1], 16, %2;\n"
                 :: "r"(saddr), "l"(gmem_src), "r"(sz));
}
#define CP_COMMIT() asm volatile("cp.async.commit_group;\n" ::: "memory")
#define CP_WAIT1()  asm volatile("cp.async.wait_group 1;\n" ::: "memory")

// ---------------- FP16 tensor-core GEMM (round-9 config: 256 thr, warp 64x32) ----------------
#define TBM 128
#define TBN 128
#define TBK 64
#define APADH 72
#define BPADH 136
#define NSTAGE 3
#define AS_STAGE (TBM * APADH)
#define BS_STAGE (TBK * BPADH)
#define GEMM_SMEM_BYTES ((NSTAGE * (AS_STAGE + BS_STAGE)) * 2)   // 107520

__device__ __forceinline__ void mma_f16(
    float& d0, float& d1, float& d2, float& d3,
    uint32_t a0, uint32_t a1, uint32_t a2, uint32_t a3,
    uint32_t b0, uint32_t b1)
{
    asm volatile(
        "mma.sync.aligned.m16n8k16.row.col.f32.f16.f16.f32 "
        "{%0,%1,%2,%3}, {%4,%5,%6,%7}, {%8,%9}, {%0,%1,%2,%3};"
        : "+f"(d0), "+f"(d1), "+f"(d2), "+f"(d3)
        : "r"(a0), "r"(a1), "r"(a2), "r"(a3), "r"(b0), "r"(b1));
}

__device__ __forceinline__ void ldsm_x4(uint32_t& r0, uint32_t& r1, uint32_t& r2, uint32_t& r3,
                                        const __half* p) {
    uint32_t addr = (uint32_t)__cvta_generic_to_shared(p);
    asm volatile("ldmatrix.sync.aligned.m8n8.x4.shared.b16 {%0,%1,%2,%3}, [%4];"
                 : "=r"(r0), "=r"(r1), "=r"(r2), "=r"(r3) : "r"(addr));
}

__device__ __forceinline__ void ldsm_x4_trans(uint32_t& r0, uint32_t& r1, uint32_t& r2, uint32_t& r3,
                                              const __half* p) {
    uint32_t addr = (uint32_t)__cvta_generic_to_shared(p);
    asm volatile("ldmatrix.sync.aligned.m8n8.x4.trans.shared.b16 {%0,%1,%2,%3}, [%4];"
                 : "=r"(r0), "=r"(r1), "=r"(r2), "=r"(r3) : "r"(addr));
}

__global__ __launch_bounds__(256, 2) void gemm_f16(
    const __half* __restrict__ A, const __half* __restrict__ W,
    const float* __restrict__ bias, void* __restrict__ Cout,
    int M, int K, int N, int relu, int out_half)
{
    extern __shared__ __half sm[];
    __half* Asm = sm;
    __half* Bsm = sm + NSTAGE * AS_STAGE;

    const int tid = threadIdx.x;
    const int bm  = blockIdx.y * TBM;
    const int bn  = blockIdx.x * TBN;

    const int row_a = tid >> 1;
    const int col_a = (tid & 1) << 5;
    const int row_b = tid >> 2;
    const int col_b = (tid & 3) << 5;

    const bool a_ok = (bm + row_a) < M;

    const int w    = tid >> 5;
    const int wm   = (w & 1) * 64;
    const int wn   = (w >> 1) * 32;
    const int lane = tid & 31;
    const int gid  = lane >> 2;
    const int tig  = lane & 3;
    const int l16  = lane & 15;
    const int lhi  = (lane >> 4) << 3;

    float acc[4][4][4] = {};

    const int KT = K >> 6;

    const __half* Abase = A + (size_t)(bm + row_a) * K + col_a;
    const __half* Bbase = W + (size_t)row_b * N + bn + col_b;

    __half* asm_dst[NSTAGE];
    __half* bsm_dst[NSTAGE];
    #pragma unroll
    for (int s = 0; s < NSTAGE; s++) {
        asm_dst[s] = Asm + s * AS_STAGE + row_a * APADH + col_a;
        bsm_dst[s] = Bsm + s * BS_STAGE + row_b * BPADH + col_b;
    }

    #pragma unroll
    for (int s = 0; s < NSTAGE - 1; s++) {
        const int k0 = s << 6;
        #pragma unroll
        for (int i = 0; i < 4; i++) {
            cp_async16(asm_dst[s] + i * 8, Abase + k0 + i * 8, a_ok);
            cp_async16(bsm_dst[s] + i * 8, Bbase + (size_t)k0 * N + i * 8, true);
        }
        CP_COMMIT();
    }

    for (int kt = 0; kt < KT; kt++) {
        CP_WAIT1();
        __syncthreads();

        if (kt + NSTAGE - 1 < KT) {
            const int s  = (kt + NSTAGE - 1) % NSTAGE;
            const int k0 = (kt + NSTAGE - 1) << 6;
            #pragma unroll
            for (int i = 0; i < 4; i++) {
                cp_async16(asm_dst[s] + i * 8, Abase + k0 + i * 8, a_ok);
                cp_async16(bsm_dst[s] + i * 8, Bbase + (size_t)k0 * N + i * 8, true);
            }
        }
        CP_COMMIT();

        const __half* Ab = Asm + (kt % NSTAGE) * AS_STAGE;
        const __half* Bb = Bsm + (kt % NSTAGE) * BS_STAGE;

        #pragma unroll
        for (int ks = 0; ks < 4; ks++) {
            const int kk = ks << 4;
            uint32_t af[4][4];
            uint32_t bf[4][2];
            #pragma unroll
            for (int mt = 0; mt < 4; mt++) {
                const int r0 = wm + mt * 16;
                ldsm_x4(af[mt][0], af[mt][1], af[mt][2], af[mt][3],
                        Ab + (size_t)(r0 + l16) * APADH + kk + lhi);
            }
            #pragma unroll
            for (int pr = 0; pr < 2; pr++) {
                const int c0 = wn + pr * 16;
                ldsm_x4_trans(bf[pr * 2][0], bf[pr * 2][1], bf[pr * 2 + 1][0], bf[pr * 2 + 1][1],
                              Bb + (size_t)(kk + l16) * BPADH + c0 + lhi);
            }
            #pragma unroll
            for (int mt = 0; mt < 4; mt++)
                #pragma unroll
                for (int nt = 0; nt < 4; nt++)
                    mma_f16(acc[mt][nt][0], acc[mt][nt][1], acc[mt][nt][2], acc[mt][nt][3],
                            af[mt][0], af[mt][1], af[mt][2], af[mt][3],
                            bf[nt][0], bf[nt][1]);
        }
    }

    float*  Cf = (float*)Cout;
    __half* Ch = (__half*)Cout;
    #pragma unroll
    for (int mt = 0; mt < 4; mt++) {
        const int r0 = bm + wm + mt * 16 + gid;
        const int r1 = r0 + 8;
        #pragma unroll
        for (int nt = 0; nt < 4; nt++) {
            const int c = bn + wn + nt * 8 + tig * 2;
            const float b0 = bias[c], b1 = bias[c + 1];
            float v0 = acc[mt][nt][0] + b0;
            float v1 = acc[mt][nt][1] + b1;
            float v2 = acc[mt][nt][2] + b0;
            float v3 = acc[mt][nt][3] + b1;
            if (relu) {
                v0 = fmaxf(v0, 0.f); v1 = fmaxf(v1, 0.f);
                v2 = fmaxf(v2, 0.f); v3 = fmaxf(v3, 0.f);
            }
            if (out_half) {
                if (r0 < M) *(__half2*)(Ch + (size_t)r0 * N + c) = __floats2half2_rn(v0, v1);
                if (r1 < M) *(__half2*)(Ch + (size_t)r1 * N + c) = __floats2half2_rn(v2, v3);
            } else {
                if (r0 < M) *(float2*)(Cf + (size_t)r0 * N + c) = make_float2(v0, v1);
                if (r1 < M) *(float2*)(Cf + (size_t)r1 * N + c) = make_float2(v2, v3);
            }
        }
    }
}

// ---------------- multi-scale deformable attention (round-9 exact, cheap batch predicate) ----------------
__global__ __launch_bounds__(256) void deform_attn_kernel(
    const __half* __restrict__ voa, const float* __restrict__ ref,
    __half* __restrict__ out)
{
    const int gw = blockIdx.x * 8 + (threadIdx.x >> 5);
    if (gw >= MROWS * 4) return;
    const int lane = threadIdx.x & 31;
    const int hp = gw & 3;
    const int bn = gw >> 2;
    const size_t vb = (bn >= NQ) ? (size_t)NQ : 0;   // batch base (no divide)
    const int h  = hp * 2 + (lane >> 4);
    const int p  = lane & 15;
    const int lvl = p >> 2;

    const __half* offp = voa + (size_t)bn * CATN + 256 + h * 32;
    float ox = __half2float(offp[p * 2 + 0]);
    float oy = __half2float(offp[p * 2 + 1]);
    float logit = __half2float(voa[(size_t)bn * CATN + 512 + h * 16 + p]);

    float mx = logit;
    #pragma unroll
    for (int o = 8; o > 0; o >>= 1) mx = fmaxf(mx, __shfl_xor_sync(0xFFFFFFFFu, mx, o));
    float e = __expf(logit - mx);
    float ss = e;
    #pragma unroll
    for (int o = 8; o > 0; o >>= 1) ss += __shfl_xor_sync(0xFFFFFFFFu, ss, o);
    const float prob = e / ss;

    const int W = c_w[lvl], H = c_h[lvl], S = c_start[lvl];
    const float fw = (float)W, fh = (float)H;
    const float rx = ref[((size_t)bn * NLVL + lvl) * 2 + 0];
    const float ry = ref[((size_t)bn * NLVL + lvl) * 2 + 1];

    const float locx = rx + ox / fw;
    const float locy = ry + oy / fh;
    const float xs = locx * fw - 0.5f;
    const float ys = locy * fh - 0.5f;
    const float fxs = floorf(xs), fys = floorf(ys);
    const int x0 = (int)fxs, y0 = (int)fys;
    const float lx = xs - fxs, ly = ys - fys;
    const int x1 = x0 + 1, y1 = y0 + 1;

    const float vx0 = (x0 >= 0 && x0 < W) ? 1.f : 0.f;
    const float vx1 = (x1 >= 0 && x1 < W) ? 1.f : 0.f;
    const float vy0 = (y0 >= 0 && y0 < H) ? 1.f : 0.f;
    const float vy1 = (y1 >= 0 && y1 < H) ? 1.f : 0.f;

    float w00 = (1.f - lx) * (1.f - ly) * prob * vy0 * vx0;
    float w01 = lx * (1.f - ly) * prob * vy0 * vx1;
    float w10 = (1.f - lx) * ly * prob * vy1 * vx0;
    float w11 = lx * ly * prob * vy1 * vx1;

    const int x0c = min(max(x0, 0), W - 1);
    const int x1c = min(max(x1, 0), W - 1);
    const int y0c = min(max(y0, 0), H - 1);
    const int y1c = min(max(y1, 0), H - 1);

    int r00 = S + y0c * W + x0c;
    int r01 = S + y0c * W + x1c;
    int r10 = S + y1c * W + x0c;
    int r11 = S + y1c * W + x1c;

    const int l16 = lane & 15;
    const __half2* vbase = (const __half2*)(voa + vb * CATN + h * HDIM) + l16;
    const int ROWH2 = CATN / 2;

    float2 acc = make_float2(0.f, 0.f);

    #pragma unroll
    for (int q = 0; q < 16; q++) {
        const int   i00 = __shfl_sync(0xFFFFFFFFu, r00, q, 16);
        const int   i01 = __shfl_sync(0xFFFFFFFFu, r01, q, 16);
        const int   i10 = __shfl_sync(0xFFFFFFFFu, r10, q, 16);
        const int   i11 = __shfl_sync(0xFFFFFFFFu, r11, q, 16);
        const float a00 = __shfl_sync(0xFFFFFFFFu, w00, q, 16);
        const float a01 = __shfl_sync(0xFFFFFFFFu, w01, q, 16);
        const float a10 = __shfl_sync(0xFFFFFFFFu, w10, q, 16);
        const float a11 = __shfl_sync(0xFFFFFFFFu, w11, q, 16);

        const float2 f00 = __half22float2(vbase[(size_t)i00 * ROWH2]);
        const float2 f01 = __half22float2(vbase[(size_t)i01 * ROWH2]);
        const float2 f10 = __half22float2(vbase[(size_t)i10 * ROWH2]);
        const float2 f11 = __half22float2(vbase[(size_t)i11 * ROWH2]);

        acc.x += a00 * f00.x + a01 * f01.x + a10 * f10.x + a11 * f11.x;
        acc.y += a00 * f00.y + a01 * f01.y + a10 * f10.y + a11 * f11.y;
    }

    __half2* op = (__half2*)(out + (size_t)bn * E_ + h * HDIM) + l16;
    *op = __floats2half2_rn(acc.x, acc.y);
}

// ---------------- fused residual add + LayerNorm (warp per row) ----------------
__global__ __launch_bounds__(256) void add_ln_kernel(
    const float* __restrict__ x, const float* __restrict__ r,
    const float* __restrict__ gamma, const float* __restrict__ beta,
    float* __restrict__ out_f, __half* __restrict__ out_h, int M)
{
    int row = blockIdx.x * 8 + (threadIdx.x >> 5);
    if (row >= M) return;
    int lane = threadIdx.x & 31;

    const float* xp = x + (size_t)row * E_;
    const float* rp = r + (size_t)row * E_;

    float vals[8];
    float s = 0.f;
    #pragma unroll
    for (int i = 0; i < 8; i++) {
        vals[i] = xp[lane + i * 32] + rp[lane + i * 32];
        s += vals[i];
    }
    #pragma unroll
    for (int o = 16; o > 0; o >>= 1) s += __shfl_xor_sync(0xFFFFFFFFu, s, o);
    float mean = s * (1.f / E_);

    float vs = 0.f;
    #pragma unroll
    for (int i = 0; i < 8; i++) {
        float d = vals[i] - mean;
        vs += d * d;
    }
    #pragma unroll
    for (int o = 16; o > 0; o >>= 1) vs += __shfl_xor_sync(0xFFFFFFFFu, vs, o);
    float inv = rsqrtf(vs * (1.f / E_) + EPS);

    float* opf = out_f + (size_t)row * E_;
    #pragma unroll
    for (int i = 0; i < 8; i++) {
        int c = lane + i * 32;
        float v = (vals[i] - mean) * inv * gamma[c] + beta[c];
        opf[c] = v;
        if (out_h) out_h[(size_t)row * E_ + c] = __float2half(v);
    }
}

// ---------------- launcher ----------------
static inline void run_gemm(const __half* A, const __half* W, const float* b,
                            void* C, int M, int K, int Nc, int relu, int out_half) {
    dim3 grid(Nc / TBN, (M + TBM - 1) / TBM);
    gemm_f16<<<grid, 256, GEMM_SMEM_BYTES>>>(A, W, b, C, M, K, Nc, relu, out_half);
}

extern "C" void kernel_launch(void* const* d_in, const int* in_sizes, int n_in,
                              void* d_out, int out_size) {
    const float* src  = (const float*)d_in[0];
    const float* ref  = (const float*)d_in[1];
    const float* Woff = (const float*)d_in[4];
    const float* boff = (const float*)d_in[5];
    const float* Waw  = (const float*)d_in[6];
    const float* baw  = (const float*)d_in[7];
    const float* Wv   = (const float*)d_in[8];
    const float* bv   = (const float*)d_in[9];
    const float* Wo   = (const float*)d_in[10];
    const float* bo   = (const float*)d_in[11];
    const float* ln1g = (const float*)d_in[12];
    const float* ln1b = (const float*)d_in[13];
    const float* Wf1  = (const float*)d_in[14];
    const float* bf1  = (const float*)d_in[15];
    const float* Wf2  = (const float*)d_in[16];
    const float* bf2  = (const float*)d_in[17];
    const float* ln2g = (const float*)d_in[18];
    const float* ln2b = (const float*)d_in[19];
    float* out = (float*)d_out;

    cudaFuncSetAttribute(gemm_f16, cudaFuncAttributeMaxDynamicSharedMemorySize, GEMM_SMEM_BYTES);

    float *px, *ptmp, *pbcat;
    __half *pxh, *pvoa, *psamp, *pffn, *pwcat, *pwo, *pwf1, *pwf2;
    cudaGetSymbolAddress((void**)&px,    g_x);
    cudaGetSymbolAddress((void**)&pxh,   g_xh);
    cudaGetSymbolAddress((void**)&pvoa,  g_voa);
    cudaGetSymbolAddress((void**)&psamp, g_samp);
    cudaGetSymbolAddress((void**)&ptmp,  g_tmp);
    cudaGetSymbolAddress((void**)&pffn,  g_ffn);
    cudaGetSymbolAddress((void**)&pwcat, g_wcat);
    cudaGetSymbolAddress((void**)&pbcat, g_bcat);
    cudaGetSymbolAddress((void**)&pwo,   g_wo);
    cudaGetSymbolAddress((void**)&pwf1,  g_wf1);
    cudaGetSymbolAddress((void**)&pwf2,  g_wf2);

    const int M = MROWS;

    prep_all_kernel<<<(PREP_TOTAL + 255) / 256, 256>>>(
        src, Wv, Woff, Waw, bv, boff, baw, Wo, Wf1, Wf2,
        px, pxh, pwcat, pbcat, pwo, pwf1, pwf2);

    const int dwarps = M * 4;
    const int dgrid  = (dwarps + 7) / 8;

    for (int layer = 0; layer < 6; layer++) {
        // fused projections: [v | off | aw-logits], fp16 out
        run_gemm(pxh, pwcat, pbcat, pvoa, M, E_, CATN, 0, 1);

        deform_attn_kernel<<<dgrid, 256>>>(pvoa, ref, psamp);

        run_gemm(psamp, pwo, bo, ptmp, M, E_, E_, 0, 0);                 // fp32 out
        add_ln_kernel<<<(M + 7) / 8, 256>>>(px, ptmp, ln1g, ln1b, px, pxh, M);

        run_gemm(pxh,  pwf1, bf1, pffn, M, E_, F_, 1, 1);                // relu, fp16 out
        run_gemm(pffn, pwf2, bf2, ptmp, M, F_, E_, 0, 0);                // fp32 out

        float* dst = (layer == 5) ? out : px;
        __half* dsth = (layer == 5) ? (__half*)nullptr : pxh;
        add_ln_kernel<<<(M + 7) / 8, 256>>>(px, ptmp, ln2g, ln2b, dst, dsth, M);
    }
}

// round 17
// speedup vs baseline: 1.1639x; 1.0046x over previous
#include <cuda_runtime.h>
#include <cuda_fp16.h>
#include <math.h>
#include <stdint.h>

// ---------------- static problem config ----------------
#define NQ     13294
#define BATCH  2
#define MROWS  (BATCH * NQ)     // 26588
#define E_     256
#define F_     1024
#define CATN   640              // concat proj width: 256 (v) + 256 (off) + 128 (aw)
#define NHEAD  8
#define HDIM   32
#define NLVL   4
#define NPNT   4
#define EPS    1e-5f

// ---------------- scratch (static device globals; no allocation) ----------------
__device__ float  g_x   [MROWS * E_];    // fp32 residual stream
__device__ __half g_xh  [MROWS * E_];    // fp16 view for GEMM A
__device__ __half g_voa [MROWS * CATN];  // [v | off | aw-logits] fp16
__device__ __half g_samp[MROWS * E_];    // deform output (GEMM A)
__device__ float  g_tmp [MROWS * E_];    // fp32 branch output (pre-LN)
__device__ __half g_ffn [MROWS * F_];    // FFN hidden
__device__ __half g_wcat[E_ * CATN];
__device__ float  g_bcat[CATN];
__device__ __half g_wo  [E_ * E_];
__device__ __half g_wf1 [E_ * F_];
__device__ __half g_wf2 [F_ * E_];

__constant__ int c_w[NLVL]     = {100, 50, 25, 13};
__constant__ int c_h[NLVL]     = {100, 50, 25, 13};
__constant__ int c_start[NLVL] = {0, 10000, 12500, 13125};

// ---------------- single prep kernel (1 launch) ----------------
#define XCOPY_N (MROWS * E_)    // 6806528
#define WCAT_N (E_ * CATN)
#define WO_N   (E_ * E_)
#define WF1_N  (E_ * F_)
#define WF2_N  (F_ * E_)
#define PREP_TOTAL (XCOPY_N + WCAT_N + WO_N + WF1_N + WF2_N)

__global__ void prep_all_kernel(
    const float* __restrict__ src,
    const float* __restrict__ Wv, const float* __restrict__ Woff, const float* __restrict__ Waw,
    const float* __restrict__ bv, const float* __restrict__ boff, const float* __restrict__ baw,
    const float* __restrict__ Wo, const float* __restrict__ Wf1, const float* __restrict__ Wf2,
    float* __restrict__ xf, __half* __restrict__ xh,
    __half* __restrict__ wcat, float* __restrict__ bcat,
    __half* __restrict__ wo, __half* __restrict__ wf1, __half* __restrict__ wf2)
{
    int i = blockIdx.x * blockDim.x + threadIdx.x;
    if (i < XCOPY_N) {
        float v = src[i]; xf[i] = v; xh[i] = __float2half(v);
    } else if (i < XCOPY_N + WCAT_N) {
        int j = i - XCOPY_N;
        int r = j / CATN, c = j % CATN;
        float v;
        if (c < 256)      v = Wv  [r * 256 + c];
        else if (c < 512) v = Woff[r * 256 + (c - 256)];
        else              v = Waw [r * 128 + (c - 512)];
        wcat[j] = __float2half(v);
    } else if (i < XCOPY_N + WCAT_N + WO_N) {
        int j = i - XCOPY_N - WCAT_N;
        wo[j] = __float2half(Wo[j]);
    } else if (i < XCOPY_N + WCAT_N + WO_N + WF1_N) {
        int j = i - XCOPY_N - WCAT_N - WO_N;
        wf1[j] = __float2half(Wf1[j]);
    } else if (i < PREP_TOTAL) {
        int j = i - XCOPY_N - WCAT_N - WO_N - WF1_N;
        wf2[j] = __float2half(Wf2[j]);
    }
    if (i < CATN) {
        bcat[i] = (i < 256) ? bv[i] : (i < 512) ? boff[i - 256] : baw[i - 512];
    }
}

// ---------------- cp.async helpers ----------------
__device__ __forceinline__ void cp_async16(void* smem_dst, const void* gmem_src, bool pred) {
    uint32_t saddr = (uint32_t)__cvta_generic_to_shared(smem_dst);
    int sz = pred ? 16 : 0;
    asm volatile("cp.async.cg.shared.global [%0], [%1], 16, %2;\n"
                 :: "r"(saddr), "l"(gmem_src), "r"(sz));
}
#define CP_COMMIT() asm volatile("cp.async.commit_group;\n" ::: "memory")
#define CP_WAIT1()  asm volatile("cp.async.wait_group 1;\n" ::: "memory")

// ---------------- FP16 tensor-core GEMM (converged config: 256 thr, warp 64x32) ----------------
#define TBM 128
#define TBN 128
#define TBK 64
#define APADH 72
#define BPADH 136
#define NSTAGE 3
#define AS_STAGE (TBM * APADH)
#define BS_STAGE (TBK * BPADH)
#define GEMM_SMEM_BYTES ((NSTAGE * (AS_STAGE + BS_STAGE)) * 2)   // 107520

__device__ __forceinline__ void mma_f16(
    float& d0, float& d1, float& d2, float& d3,
    uint32_t a0, uint32_t a1, uint32_t a2, uint32_t a3,
    uint32_t b0, uint32_t b1)
{
    asm volatile(
        "mma.sync.aligned.m16n8k16.row.col.f32.f16.f16.f32 "
        "{%0,%1,%2,%3}, {%4,%5,%6,%7}, {%8,%9}, {%0,%1,%2,%3};"
        : "+f"(d0), "+f"(d1), "+f"(d2), "+f"(d3)
        : "r"(a0), "r"(a1), "r"(a2), "r"(a3), "r"(b0), "r"(b1));
}

__device__ __forceinline__ void ldsm_x4(uint32_t& r0, uint32_t& r1, uint32_t& r2, uint32_t& r3,
                                        const __half* p) {
    uint32_t addr = (uint32_t)__cvta_generic_to_shared(p);
    asm volatile("ldmatrix.sync.aligned.m8n8.x4.shared.b16 {%0,%1,%2,%3}, [%4];"
                 : "=r"(r0), "=r"(r1), "=r"(r2), "=r"(r3) : "r"(addr));
}

__device__ __forceinline__ void ldsm_x4_trans(uint32_t& r0, uint32_t& r1, uint32_t& r2, uint32_t& r3,
                                              const __half* p) {
    uint32_t addr = (uint32_t)__cvta_generic_to_shared(p);
    asm volatile("ldmatrix.sync.aligned.m8n8.x4.trans.shared.b16 {%0,%1,%2,%3}, [%4];"
                 : "=r"(r0), "=r"(r1), "=r"(r2), "=r"(r3) : "r"(addr));
}

__global__ __launch_bounds__(256, 2) void gemm_f16(
    const __half* __restrict__ A, const __half* __restrict__ W,
    const float* __restrict__ bias, void* __restrict__ Cout,
    int M, int K, int N, int relu, int out_half)
{
    extern __shared__ __half sm[];
    __half* Asm = sm;
    __half* Bsm = sm + NSTAGE * AS_STAGE;

    const int tid = threadIdx.x;
    const int bm  = blockIdx.y * TBM;
    const int bn  = blockIdx.x * TBN;

    const int row_a = tid >> 1;
    const int col_a = (tid & 1) << 5;
    const int row_b = tid >> 2;
    const int col_b = (tid & 3) << 5;

    const bool a_ok = (bm + row_a) < M;

    const int w    = tid >> 5;
    const int wm   = (w & 1) * 64;
    const int wn   = (w >> 1) * 32;
    const int lane = tid & 31;
    const int gid  = lane >> 2;
    const int tig  = lane & 3;
    const int l16  = lane & 15;
    const int lhi  = (lane >> 4) << 3;

    float acc[4][4][4] = {};

    const int KT = K >> 6;

    const __half* Abase = A + (size_t)(bm + row_a) * K + col_a;
    const __half* Bbase = W + (size_t)row_b * N + bn + col_b;

    __half* asm_dst[NSTAGE];
    __half* bsm_dst[NSTAGE];
    #pragma unroll
    for (int s = 0; s < NSTAGE; s++) {
        asm_dst[s] = Asm + s * AS_STAGE + row_a * APADH + col_a;
        bsm_dst[s] = Bsm + s * BS_STAGE + row_b * BPADH + col_b;
    }

    #pragma unroll
    for (int s = 0; s < NSTAGE - 1; s++) {
        const int k0 = s << 6;
        #pragma unroll
        for (int i = 0; i < 4; i++) {
            cp_async16(asm_dst[s] + i * 8, Abase + k0 + i * 8, a_ok);
            cp_async16(bsm_dst[s] + i * 8, Bbase + (size_t)k0 * N + i * 8, true);
        }
        CP_COMMIT();
    }

    for (int kt = 0; kt < KT; kt++) {
        CP_WAIT1();
        __syncthreads();

        if (kt + NSTAGE - 1 < KT) {
            const int s  = (kt + NSTAGE - 1) % NSTAGE;
            const int k0 = (kt + NSTAGE - 1) << 6;
            #pragma unroll
            for (int i = 0; i < 4; i++) {
                cp_async16(asm_dst[s] + i * 8, Abase + k0 + i * 8, a_ok);
                cp_async16(bsm_dst[s] + i * 8, Bbase + (size_t)k0 * N + i * 8, true);
            }
        }
        CP_COMMIT();

        const __half* Ab = Asm + (kt % NSTAGE) * AS_STAGE;
        const __half* Bb = Bsm + (kt % NSTAGE) * BS_STAGE;

        #pragma unroll
        for (int ks = 0; ks < 4; ks++) {
            const int kk = ks << 4;
            uint32_t af[4][4];
            uint32_t bf[4][2];
            #pragma unroll
            for (int mt = 0; mt < 4; mt++) {
                const int r0 = wm + mt * 16;
                ldsm_x4(af[mt][0], af[mt][1], af[mt][2], af[mt][3],
                        Ab + (size_t)(r0 + l16) * APADH + kk + lhi);
            }
            #pragma unroll
            for (int pr = 0; pr < 2; pr++) {
                const int c0 = wn + pr * 16;
                ldsm_x4_trans(bf[pr * 2][0], bf[pr * 2][1], bf[pr * 2 + 1][0], bf[pr * 2 + 1][1],
                              Bb + (size_t)(kk + l16) * BPADH + c0 + lhi);
            }
            #pragma unroll
            for (int mt = 0; mt < 4; mt++)
                #pragma unroll
                for (int nt = 0; nt < 4; nt++)
                    mma_f16(acc[mt][nt][0], acc[mt][nt][1], acc[mt][nt][2], acc[mt][nt][3],
                            af[mt][0], af[mt][1], af[mt][2], af[mt][3],
                            bf[nt][0], bf[nt][1]);
        }
    }

    float*  Cf = (float*)Cout;
    __half* Ch = (__half*)Cout;
    #pragma unroll
    for (int mt = 0; mt < 4; mt++) {
        const int r0 = bm + wm + mt * 16 + gid;
        const int r1 = r0 + 8;
        #pragma unroll
        for (int nt = 0; nt < 4; nt++) {
            const int c = bn + wn + nt * 8 + tig * 2;
            const float2 bv2 = *(const float2*)(bias + c);
            float v0 = acc[mt][nt][0] + bv2.x;
            float v1 = acc[mt][nt][1] + bv2.y;
            float v2 = acc[mt][nt][2] + bv2.x;
            float v3 = acc[mt][nt][3] + bv2.y;
            if (relu) {
                v0 = fmaxf(v0, 0.f); v1 = fmaxf(v1, 0.f);
                v2 = fmaxf(v2, 0.f); v3 = fmaxf(v3, 0.f);
            }
            if (out_half) {
                if (r0 < M) *(__half2*)(Ch + (size_t)r0 * N + c) = __floats2half2_rn(v0, v1);
                if (r1 < M) *(__half2*)(Ch + (size_t)r1 * N + c) = __floats2half2_rn(v2, v3);
            } else {
                if (r0 < M) *(float2*)(Cf + (size_t)r0 * N + c) = make_float2(v0, v1);
                if (r1 < M) *(float2*)(Cf + (size_t)r1 * N + c) = make_float2(v2, v3);
            }
        }
    }
}

// ---------------- multi-scale deformable attention (converged version) ----------------
__global__ __launch_bounds__(256) void deform_attn_kernel(
    const __half* __restrict__ voa, const float* __restrict__ ref,
    __half* __restrict__ out)
{
    const int gw = blockIdx.x * 8 + (threadIdx.x >> 5);
    if (gw >= MROWS * 4) return;
    const int lane = threadIdx.x & 31;
    const int hp = gw & 3;
    const int bn = gw >> 2;
    const size_t vb = (bn >= NQ) ? (size_t)NQ : 0;   // batch base (no divide)
    const int h  = hp * 2 + (lane >> 4);
    const int p  = lane & 15;
    const int lvl = p >> 2;

    const __half* offp = voa + (size_t)bn * CATN + 256 + h * 32;
    float ox = __half2float(offp[p * 2 + 0]);
    float oy = __half2float(offp[p * 2 + 1]);
    float logit = __half2float(voa[(size_t)bn * CATN + 512 + h * 16 + p]);

    float mx = logit;
    #pragma unroll
    for (int o = 8; o > 0; o >>= 1) mx = fmaxf(mx, __shfl_xor_sync(0xFFFFFFFFu, mx, o));
    float e = __expf(logit - mx);
    float ss = e;
    #pragma unroll
    for (int o = 8; o > 0; o >>= 1) ss += __shfl_xor_sync(0xFFFFFFFFu, ss, o);
    const float prob = __fdividef(e, ss);

    const int W = c_w[lvl], H = c_h[lvl], S = c_start[lvl];
    const float fw = (float)W, fh = (float)H;
    const float rx = ref[((size_t)bn * NLVL + lvl) * 2 + 0];
    const float ry = ref[((size_t)bn * NLVL + lvl) * 2 + 1];

    const float locx = rx + ox / fw;
    const float locy = ry + oy / fh;
    const float xs = locx * fw - 0.5f;
    const float ys = locy * fh - 0.5f;
    const float fxs = floorf(xs), fys = floorf(ys);
    const int x0 = (int)fxs, y0 = (int)fys;
    const float lx = xs - fxs, ly = ys - fys;
    const int x1 = x0 + 1, y1 = y0 + 1;

    const float vx0 = (x0 >= 0 && x0 < W) ? 1.f : 0.f;
    const float vx1 = (x1 >= 0 && x1 < W) ? 1.f : 0.f;
    const float vy0 = (y0 >= 0 && y0 < H) ? 1.f : 0.f;
    const float vy1 = (y1 >= 0 && y1 < H) ? 1.f : 0.f;

    float w00 = (1.f - lx) * (1.f - ly) * prob * vy0 * vx0;
    float w01 = lx * (1.f - ly) * prob * vy0 * vx1;
    float w10 = (1.f - lx) * ly * prob * vy1 * vx0;
    float w11 = lx * ly * prob * vy1 * vx1;

    const int x0c = min(max(x0, 0), W - 1);
    const int x1c = min(max(x1, 0), W - 1);
    const int y0c = min(max(y0, 0), H - 1);
    const int y1c = min(max(y1, 0), H - 1);

    int r00 = S + y0c * W + x0c;
    int r01 = S + y0c * W + x1c;
    int r10 = S + y1c * W + x0c;
    int r11 = S + y1c * W + x1c;

    const int l16 = lane & 15;
    const __half2* vbase = (const __half2*)(voa + vb * CATN + h * HDIM) + l16;
    const int ROWH2 = CATN / 2;

    float2 acc = make_float2(0.f, 0.f);

    #pragma unroll
    for (int q = 0; q < 16; q++) {
        const int   i00 = __shfl_sync(0xFFFFFFFFu, r00, q, 16);
        const int   i01 = __shfl_sync(0xFFFFFFFFu, r01, q, 16);
        const int   i10 = __shfl_sync(0xFFFFFFFFu, r10, q, 16);
        const int   i11 = __shfl_sync(0xFFFFFFFFu, r11, q, 16);
        const float a00 = __shfl_sync(0xFFFFFFFFu, w00, q, 16);
        const float a01 = __shfl_sync(0xFFFFFFFFu, w01, q, 16);
        const float a10 = __shfl_sync(0xFFFFFFFFu, w10, q, 16);
        const float a11 = __shfl_sync(0xFFFFFFFFu, w11, q, 16);

        const float2 f00 = __half22float2(vbase[(size_t)i00 * ROWH2]);
        const float2 f01 = __half22float2(vbase[(size_t)i01 * ROWH2]);
        const float2 f10 = __half22float2(vbase[(size_t)i10 * ROWH2]);
        const float2 f11 = __half22float2(vbase[(size_t)i11 * ROWH2]);

        acc.x += a00 * f00.x + a01 * f01.x + a10 * f10.x + a11 * f11.x;
        acc.y += a00 * f00.y + a01 * f01.y + a10 * f10.y + a11 * f11.y;
    }

    __half2* op = (__half2*)(out + (size_t)bn * E_ + h * HDIM) + l16;
    *op = __floats2half2_rn(acc.x, acc.y);
}

// ---------------- fused residual add + LayerNorm (warp per row) ----------------
__global__ __launch_bounds__(256) void add_ln_kernel(
    const float* __restrict__ x, const float* __restrict__ r,
    const float* __restrict__ gamma, const float* __restrict__ beta,
    float* __restrict__ out_f, __half* __restrict__ out_h, int M)
{
    int row = blockIdx.x * 8 + (threadIdx.x >> 5);
    if (row >= M) return;
    int lane = threadIdx.x & 31;

    const float* xp = x + (size_t)row * E_;
    const float* rp = r + (size_t)row * E_;

    float vals[8];
    float s = 0.f;
    #pragma unroll
    for (int i = 0; i < 8; i++) {
        vals[i] = xp[lane + i * 32] + rp[lane + i * 32];
        s += vals[i];
    }
    #pragma unroll
    for (int o = 16; o > 0; o >>= 1) s += __shfl_xor_sync(0xFFFFFFFFu, s, o);
    float mean = s * (1.f / E_);

    float vs = 0.f;
    #pragma unroll
    for (int i = 0; i < 8; i++) {
        float d = vals[i] - mean;
        vs += d * d;
    }
    #pragma unroll
    for (int o = 16; o > 0; o >>= 1) vs += __shfl_xor_sync(0xFFFFFFFFu, vs, o);
    float inv = rsqrtf(vs * (1.f / E_) + EPS);

    float* opf = out_f + (size_t)row * E_;
    #pragma unroll
    for (int i = 0; i < 8; i++) {
        int c = lane + i * 32;
        float v = (vals[i] - mean) * inv * gamma[c] + beta[c];
        opf[c] = v;
        if (out_h) out_h[(size_t)row * E_ + c] = __float2half(v);
    }
}

// ---------------- launcher ----------------
static inline void run_gemm(const __half* A, const __half* W, const float* b,
                            void* C, int M, int K, int Nc, int relu, int out_half) {
    dim3 grid(Nc / TBN, (M + TBM - 1) / TBM);
    gemm_f16<<<grid, 256, GEMM_SMEM_BYTES>>>(A, W, b, C, M, K, Nc, relu, out_half);
}

extern "C" void kernel_launch(void* const* d_in, const int* in_sizes, int n_in,
                              void* d_out, int out_size) {
    const float* src  = (const float*)d_in[0];
    const float* ref  = (const float*)d_in[1];
    const float* Woff = (const float*)d_in[4];
    const float* boff = (const float*)d_in[5];
    const float* Waw  = (const float*)d_in[6];
    const float* baw  = (const float*)d_in[7];
    const float* Wv   = (const float*)d_in[8];
    const float* bv   = (const float*)d_in[9];
    const float* Wo   = (const float*)d_in[10];
    const float* bo   = (const float*)d_in[11];
    const float* ln1g = (const float*)d_in[12];
    const float* ln1b = (const float*)d_in[13];
    const float* Wf1  = (const float*)d_in[14];
    const float* bf1  = (const float*)d_in[15];
    const float* Wf2  = (const float*)d_in[16];
    const float* bf2  = (const float*)d_in[17];
    const float* ln2g = (const float*)d_in[18];
    const float* ln2b = (const float*)d_in[19];
    float* out = (float*)d_out;

    cudaFuncSetAttribute(gemm_f16, cudaFuncAttributeMaxDynamicSharedMemorySize, GEMM_SMEM_BYTES);

    float *px, *ptmp, *pbcat;
    __half *pxh, *pvoa, *psamp, *pffn, *pwcat, *pwo, *pwf1, *pwf2;
    cudaGetSymbolAddress((void**)&px,    g_x);
    cudaGetSymbolAddress((void**)&pxh,   g_xh);
    cudaGetSymbolAddress((void**)&pvoa,  g_voa);
    cudaGetSymbolAddress((void**)&psamp, g_samp);
    cudaGetSymbolAddress((void**)&ptmp,  g_tmp);
    cudaGetSymbolAddress((void**)&pffn,  g_ffn);
    cudaGetSymbolAddress((void**)&pwcat, g_wcat);
    cudaGetSymbolAddress((void**)&pbcat, g_bcat);
    cudaGetSymbolAddress((void**)&pwo,   g_wo);
    cudaGetSymbolAddress((void**)&pwf1,  g_wf1);
    cudaGetSymbolAddress((void**)&pwf2,  g_wf2);

    const int M = MROWS;

    prep_all_kernel<<<(PREP_TOTAL + 255) / 256, 256>>>(
        src, Wv, Woff, Waw, bv, boff, baw, Wo, Wf1, Wf2,
        px, pxh, pwcat, pbcat, pwo, pwf1, pwf2);

    const int dwarps = M * 4;
    const int dgrid  = (dwarps + 7) / 8;

    for (int layer = 0; layer < 6; layer++) {
        // fused projections: [v | off | aw-logits], fp16 out
        run_gemm(pxh, pwcat, pbcat, pvoa, M, E_, CATN, 0, 1);

        deform_attn_kernel<<<dgrid, 256>>>(pvoa, ref, psamp);

        run_gemm(psamp, pwo, bo, ptmp, M, E_, E_, 0, 0);                 // fp32 out
        add_ln_kernel<<<(M + 7) / 8, 256>>>(px, ptmp, ln1g, ln1b, px, pxh, M);

        run_gemm(pxh,  pwf1, bf1, pffn, M, E_, F_, 1, 1);                // relu, fp16 out
        run_gemm(pffn, pwf2, bf2, ptmp, M, F_, E_, 0, 0);                // fp32 out

        float* dst = (layer == 5) ? out : px;
        __half* dsth = (layer == 5) ? (__half*)nullptr : pxh;
        add_ln_kernel<<<(M + 7) / 8, 256>>>(px, ptmp, ln2g, ln2b, dst, dsth, M);
    }
}